// round 16
// baseline (speedup 1.0000x reference)
#include <cuda_runtime.h>
#include <cuda_fp16.h>
#include <math.h>
#include <stdint.h>

#define NB 2
#define NS 1024
#define NT (NB*NS)      // 2048 tokens
#define ND 2048
#define NF 8192
#define NE 4

// ---------------- persistent scratch (device globals) ----------------------
__device__ float    g_gatew[NE*NT];
__device__ int      g_counts[NE];
__device__ int      g_lists[NE*NT];
__device__ __half   g_Xh[(size_t)NT*ND];          // x, fp16 (k-contiguous rows)
__device__ __half   g_Hh[(size_t)NE*NT*NF];       // H = silu(G)*U fp16; rows >= Me stay 0
__device__ __half   g_WgT[(size_t)NE*NF*ND];      // Wg^T fp16 [E][N=F][K=D]
__device__ __half   g_WuT[(size_t)NE*NF*ND];      // Wu^T fp16 [E][N=F][K=D]
__device__ __half   g_WdT[(size_t)NE*ND*NF];      // Wd^T fp16 [E][N=D][K=F]

// ---------------- helpers ---------------------------------------------------
__device__ __forceinline__ uint32_t smem_u32(const void* p) {
    uint32_t a;
    asm("{ .reg .u64 t; cvta.to.shared.u64 t, %1; cvt.u32.u64 %0, t; }" : "=r"(a) : "l"(p));
    return a;
}
__device__ __forceinline__ uint32_t packh2(float lo, float hi) {
    __half2 h = __float22half2_rn(make_float2(lo, hi));   // lo -> low half (lower k)
    return *reinterpret_cast<uint32_t*>(&h);
}
__device__ __forceinline__ void cpa16(uint32_t dst, const void* src) {
    asm volatile("cp.async.cg.shared.global [%0], [%1], 16;" :: "r"(dst), "l"(src));
}
__device__ __forceinline__ void cpa_commit() { asm volatile("cp.async.commit_group;"); }
__device__ __forceinline__ void cpa_wait1()  { asm volatile("cp.async.wait_group 1;"); }

__device__ __forceinline__ void mma16(float c[4], const unsigned a[4],
                                      unsigned b0, unsigned b1) {
    asm volatile(
        "mma.sync.aligned.m16n8k16.row.col.f32.f16.f16.f32 "
        "{%0,%1,%2,%3}, {%4,%5,%6,%7}, {%8,%9}, {%0,%1,%2,%3};"
        : "+f"(c[0]), "+f"(c[1]), "+f"(c[2]), "+f"(c[3])
        : "r"(a[0]), "r"(a[1]), "r"(a[2]), "r"(a[3]), "r"(b0), "r"(b1));
}
__device__ __forceinline__ void ldm4(unsigned r[4], uint32_t addr) {
    asm volatile("ldmatrix.sync.aligned.m8n8.x4.shared.b16 {%0,%1,%2,%3}, [%4];"
        : "=r"(r[0]), "=r"(r[1]), "=r"(r[2]), "=r"(r[3]) : "r"(addr));
}

// ---------------- prep: zero out + counts, x -> fp16 ------------------------
__global__ void prep_kernel(const float* __restrict__ x, float* __restrict__ out) {
    const size_t n4 = (size_t)NT * ND / 4;
    const float4 z = make_float4(0.f, 0.f, 0.f, 0.f);
    for (size_t i = blockIdx.x * (size_t)blockDim.x + threadIdx.x; i < n4;
         i += (size_t)gridDim.x * blockDim.x) {
        ((float4*)out)[i] = z;
        float4 v = ((const float4*)x)[i];
        uint2 o;
        o.x = packh2(v.x, v.y);
        o.y = packh2(v.z, v.w);
        ((uint2*)g_Xh)[i] = o;
    }
    if (blockIdx.x == 0 && threadIdx.x < NE) g_counts[threadIdx.x] = 0;
}

// ---------------- router (+ fused compaction) -------------------------------
__global__ void router_kernel(const float* __restrict__ x, const float* __restrict__ Wr) {
    int t = blockIdx.x;
    const float* xr = x + (size_t)t * ND;
    float acc[NE] = {0.f, 0.f, 0.f, 0.f};
    for (int d = threadIdx.x; d < ND; d += blockDim.x) {
        float xv = xr[d];
        float4 w = *(const float4*)(Wr + d * NE);
        acc[0] += xv * w.x; acc[1] += xv * w.y; acc[2] += xv * w.z; acc[3] += xv * w.w;
    }
    __shared__ float sred[NE][8];
    int lane = threadIdx.x & 31, wid = threadIdx.x >> 5;
    #pragma unroll
    for (int e = 0; e < NE; e++) {
        float s = acc[e];
        #pragma unroll
        for (int off = 16; off > 0; off >>= 1) s += __shfl_down_sync(0xffffffffu, s, off);
        if (lane == 0) sred[e][wid] = s;
    }
    __syncthreads();
    if (threadIdx.x == 0) {
        float l[NE];
        #pragma unroll
        for (int e = 0; e < NE; e++) {
            float s = 0.f;
            #pragma unroll
            for (int w = 0; w < 8; w++) s += sred[e][w];
            l[e] = s;
        }
        float mx = fmaxf(fmaxf(l[0], l[1]), fmaxf(l[2], l[3]));
        float ex[NE], ssum = 0.f;
        #pragma unroll
        for (int e = 0; e < NE; e++) { ex[e] = expf(l[e] - mx); ssum += ex[e]; }
        float p[NE];
        #pragma unroll
        for (int e = 0; e < NE; e++) p[e] = ex[e] / ssum;
        int i1 = 0;
        #pragma unroll
        for (int e = 1; e < NE; e++) if (p[e] > p[i1]) i1 = e;
        int i2 = -1;
        #pragma unroll
        for (int e = 0; e < NE; e++)
            if (e != i1 && (i2 < 0 || p[e] > p[i2])) i2 = e;
        #pragma unroll
        for (int e = 0; e < NE; e++) {
            bool sel = (e == i1 || e == i2);
            g_gatew[e * NT + t] = sel ? p[e] : 0.f;
            if (sel) {
                int pos = atomicAdd(&g_counts[e], 1);
                g_lists[e * NT + pos] = t;
            }
        }
    }
}

// ---------------- weight transpose + fp16 pack ------------------------------
__global__ __launch_bounds__(256) void wpack_kernel(const float* __restrict__ Wg,
                                                    const float* __restrict__ Wu,
                                                    const float* __restrict__ Wd) {
    __shared__ float s[32][33];
    const int TPM = NE * 16384;
    int bid = blockIdx.x;
    const int m = bid / TPM;               // 0=Wg 1=Wu 2=Wd
    int r = bid % TPM;
    const int e = r / 16384;
    const int t = r % 16384;
    int K, N;
    const float* src;
    __half* dst;
    if (m == 0)      { K = ND; N = NF; src = Wg; dst = g_WgT; }
    else if (m == 1) { K = ND; N = NF; src = Wu; dst = g_WuT; }
    else             { K = NF; N = ND; src = Wd; dst = g_WdT; }
    const int ntiles = N / 32;
    const int tn = t % ntiles, tk = t / ntiles;
    const int k0 = tk * 32, n0 = tn * 32;
    src += (size_t)e * K * N;
    dst += (size_t)e * K * N;

    const int x = threadIdx.x, y = threadIdx.y;
    #pragma unroll
    for (int j = 0; j < 4; j++)
        s[y + 8*j][x] = src[(size_t)(k0 + y + 8*j) * N + n0 + x];
    __syncthreads();
    const int tid = y * 32 + x;
    #pragma unroll
    for (int jj = 0; jj < 2; jj++) {
        const int w  = tid + jj * 256;
        const int rr = w >> 4;
        const int c2 = w & 15;
        uint32_t v = packh2(s[2*c2][rr], s[2*c2 + 1][rr]);
        *(uint32_t*)(dst + (size_t)(n0 + rr) * K + k0 + 2*c2) = v;
    }
}

// ---------------------------------------------------------------------------
// GATE+UP fused GEMM (fp16 m16n8k16, all-ldmatrix, cp.async 3-stage, BK=64,
// 256 thr, 1 CTA/SM, BIG warptile). Block tile M=128, N=128 per matrix
// (G rows 0..127, U rows 128..255 of B region). Warp grid 2(M) x 4(N),
// warptile 64x64 (acc = 128 regs). wn<2 -> G warp, wn>=2 -> U warp.
// Row stride 144 B (36 words == 4 mod 32 -> conflict-free ldmatrix).
// ---------------------------------------------------------------------------
#define RS 144                           // row stride bytes (64 halves + 8 pad)
#define GU_AB (128*RS)                   // 18432
#define GU_BROWS 256                     // G 128 + U 128
#define GU_BB (GU_BROWS*RS)              // 36864
#define GU_STAGE (GU_AB + GU_BB)         // 55296 B
#define GU_SMEM (3 * GU_STAGE)           // 165888 B

__global__ __launch_bounds__(256, 1) void gateup_tc() {
    const int e  = blockIdx.z;
    const int Me = g_counts[e];
    const int m0 = blockIdx.x * 128;
    if (m0 >= Me) return;
    const int n0 = blockIdx.y * 128;     // per-matrix n offset

    extern __shared__ char smem[];
    const uint32_t sb0 = smem_u32(smem);

    const int tid  = threadIdx.x;
    const int warp = tid >> 5;
    const int lane = tid & 31;
    const int g4   = lane >> 2;
    const int t4   = lane & 3;
    const int wm   = warp >> 2;        // 0..1
    const int wn   = warp & 3;         // 0..3
    const int mat  = wn >> 1;          // 0=G, 1=U
    const int hn   = wn & 1;           // 64-col half within matrix

    // A staging: chunks c = j*256+tid (j=0..3): row = c>>3 (0..127), ch = c&7
    const int arow = tid >> 3, ach = tid & 7;
    const __half* asrc[4];
    #pragma unroll
    for (int j = 0; j < 4; j++) {
        int mrow = m0 + arow + j * 32; if (mrow >= Me) mrow = Me - 1;
        asrc[j] = g_Xh + (size_t)g_lists[e * NT + mrow] * ND + ach * 8;
    }
    const uint32_t adst0 = sb0 + arow * RS + ach * 16;
    // B staging: 2048 chunks = 8/thread: rows brow + j*32; j<4 -> G, j>=4 -> U
    const __half* bgsrc = g_WgT + ((size_t)e * NF + n0 + arow) * ND + ach * 8;
    const __half* busrc = g_WuT + ((size_t)e * NF + n0 + arow) * ND + ach * 8;
    const uint32_t bdst0 = sb0 + GU_AB + arow * RS + ach * 16;

    float acc[4][8][4];
    #pragma unroll
    for (int i = 0; i < 4; i++)
        #pragma unroll
        for (int j = 0; j < 8; j++)
            #pragma unroll
            for (int k = 0; k < 4; k++) acc[i][j][k] = 0.f;

    const int KT = ND / 64;    // 32
    auto issue = [&](int it) {
        const uint32_t so = (uint32_t)(it % 3) * GU_STAGE;
        const size_t   ka = (size_t)it * 64;
        #pragma unroll
        for (int j = 0; j < 4; j++)
            cpa16(adst0 + so + j * 32 * RS, asrc[j] + ka);
        #pragma unroll
        for (int j = 0; j < 4; j++)
            cpa16(bdst0 + so + j * 32 * RS, bgsrc + (size_t)j * 32 * ND + ka);
        #pragma unroll
        for (int j = 0; j < 4; j++)
            cpa16(bdst0 + so + (128 + j * 32) * RS, busrc + (size_t)j * 32 * ND + ka);
    };

    issue(0); cpa_commit();
    issue(1); cpa_commit();

    // ldmatrix bases
    const uint32_t aldm = (wm * 64 + (lane & 15)) * RS + ((lane >> 4) * 16);
    const uint32_t bldm = GU_AB +
        (mat * 128 + hn * 64 + ((lane >> 4) << 3) + (lane & 7)) * RS +
        (((lane >> 3) & 1) * 16);

    for (int it = 0; it < KT; ++it) {
        cpa_wait1();               // groups {it, it+1} pending -> group it complete
        __syncthreads();
        if (it + 2 < KT) issue(it + 2);
        cpa_commit();

        const uint32_t st = sb0 + (uint32_t)(it % 3) * GU_STAGE;

        #pragma unroll
        for (int s = 0; s < 4; s++) {          // four k16 slices
            unsigned a[4][4];
            #pragma unroll
            for (int mi = 0; mi < 4; mi++)
                ldm4(a[mi], st + aldm + mi * 16 * RS + s * 32);
            #pragma unroll
            for (int p = 0; p < 4; p++) {      // ni pairs 2p, 2p+1
                unsigned bf[4];
                ldm4(bf, st + bldm + p * 16 * RS + s * 32);
                #pragma unroll
                for (int mi = 0; mi < 4; mi++) {
                    mma16(acc[mi][2*p],     a[mi], bf[0], bf[1]);
                    mma16(acc[mi][2*p + 1], a[mi], bf[2], bf[3]);
                }
            }
        }
    }

    // ---- epilogue: U warps stash; G warps write Hh = fp16(silu(G)*U) ----
    __syncthreads();
    float* Us = (float*)smem;                  // [128][132]
    if (mat == 1) {
        #pragma unroll
        for (int mi = 0; mi < 4; mi++)
            #pragma unroll
            for (int half = 0; half < 2; half++) {
                const int ml = wm * 64 + mi * 16 + g4 + half * 8;
                #pragma unroll
                for (int ni = 0; ni < 8; ni++) {
                    const int col = hn * 64 + ni * 8 + 2 * t4;
                    *(float2*)(Us + ml * 132 + col) =
                        make_float2(acc[mi][ni][half * 2], acc[mi][ni][half * 2 + 1]);
                }
            }
    }
    __syncthreads();
    if (mat == 0) {
        #pragma unroll
        for (int mi = 0; mi < 4; mi++)
            #pragma unroll
            for (int half = 0; half < 2; half++) {
                const int ml = wm * 64 + mi * 16 + g4 + half * 8;
                const int m  = m0 + ml;
                if (m >= Me) continue;
                __half* Hrow = g_Hh + ((size_t)e * NT + m) * NF + n0;
                #pragma unroll
                for (int ni = 0; ni < 8; ni++) {
                    const int col = hn * 64 + ni * 8 + 2 * t4;
                    float2 u = *(const float2*)(Us + ml * 132 + col);
                    float gv0 = acc[mi][ni][half * 2], gv1 = acc[mi][ni][half * 2 + 1];
                    float h0 = gv0 / (1.f + expf(-gv0)) * u.x;
                    float h1 = gv1 / (1.f + expf(-gv1)) * u.y;
                    *(uint32_t*)(Hrow + col) = packh2(h0, h1);
                }
            }
    }
}

// ---------------------------------------------------------------------------
// DOWN GEMM + combine (fp16 m16n8k16, all-ldmatrix, cp.async 3-stage, BK=64,
// 256 thr, 2 CTA/SM) — unchanged validated R15 config.
// Block tile 128x128. Warp grid 2(M)x4(N): warptile 64x32.
// ---------------------------------------------------------------------------
#define DN_AB (128*RS)                   // 18432
#define DN_BB (128*RS)                   // 18432
#define DN_STAGE (DN_AB + DN_BB)         // 36864 B
#define DN_SMEM (3 * DN_STAGE)           // 110592 B

__global__ __launch_bounds__(256, 2) void down_tc(float* __restrict__ OUT) {
    const int e  = blockIdx.z;
    const int Me = g_counts[e];
    const int m0 = blockIdx.x * 128;
    if (m0 >= Me) return;
    const int n0 = blockIdx.y * 128;

    extern __shared__ char smem[];
    const uint32_t sb0 = smem_u32(smem);

    const int tid  = threadIdx.x;
    const int warp = tid >> 5;
    const int lane = tid & 31;
    const int g4   = lane >> 2;
    const int t4   = lane & 3;
    const int wm   = warp >> 2;        // 0..1
    const int wn   = warp & 3;         // 0..3

    const int arow = tid >> 3, ach = tid & 7;
    const __half* asrc = g_Hh + ((size_t)e * NT + m0 + arow) * NF + ach * 8;  // rows>=Me zeros
    const uint32_t adst0 = sb0 + arow * RS + ach * 16;
    const __half* bsrc = g_WdT + ((size_t)e * ND + n0 + arow) * NF + ach * 8;
    const uint32_t bdst0 = sb0 + DN_AB + arow * RS + ach * 16;

    float acc[4][4][4];
    #pragma unroll
    for (int i = 0; i < 4; i++)
        #pragma unroll
        for (int j = 0; j < 4; j++)
            #pragma unroll
            for (int k = 0; k < 4; k++) acc[i][j][k] = 0.f;

    const int KT = NF / 64;   // 128
    auto issue = [&](int it) {
        const uint32_t so = (uint32_t)(it % 3) * DN_STAGE;
        const size_t   ka = (size_t)it * 64;
        #pragma unroll
        for (int j = 0; j < 4; j++) {
            cpa16(adst0 + so + j * 32 * RS, asrc + (size_t)j * 32 * NF + ka);
            cpa16(bdst0 + so + j * 32 * RS, bsrc + (size_t)j * 32 * NF + ka);
        }
    };

    issue(0); cpa_commit();
    issue(1); cpa_commit();

    const uint32_t aldm = (wm * 64 + (lane & 15)) * RS + ((lane >> 4) * 16);
    const uint32_t bldm = DN_AB +
        (wn * 32 + ((lane >> 4) << 3) + (lane & 7)) * RS + (((lane >> 3) & 1) * 16);

    for (int it = 0; it < KT; ++it) {
        cpa_wait1();
        __syncthreads();
        if (it + 2 < KT) issue(it + 2);
        cpa_commit();

        const uint32_t st = sb0 + (uint32_t)(it % 3) * DN_STAGE;

        #pragma unroll
        for (int s = 0; s < 4; s++) {
            unsigned a[4][4];
            #pragma unroll
            for (int mi = 0; mi < 4; mi++)
                ldm4(a[mi], st + aldm + mi * 16 * RS + s * 32);
            #pragma unroll
            for (int p = 0; p < 2; p++) {
                unsigned bf[4];
                ldm4(bf, st + bldm + p * 16 * RS + s * 32);
                #pragma unroll
                for (int mi = 0; mi < 4; mi++) {
                    mma16(acc[mi][2*p],     a[mi], bf[0], bf[1]);
                    mma16(acc[mi][2*p + 1], a[mi], bf[2], bf[3]);
                }
            }
        }
    }

    #pragma unroll
    for (int mi = 0; mi < 4; mi++) {
        #pragma unroll
        for (int half = 0; half < 2; half++) {
            const int m = m0 + wm * 64 + mi * 16 + g4 + half * 8;
            if (m >= Me) continue;
            const int tok = g_lists[e * NT + m];
            const float w = g_gatew[e * NT + tok];
            float* dst = OUT + (size_t)tok * ND + n0 + wn * 32;
            #pragma unroll
            for (int ni = 0; ni < 4; ni++) {
                atomicAdd(dst + ni * 8 + 2 * t4,     w * acc[mi][ni][half * 2]);
                atomicAdd(dst + ni * 8 + 2 * t4 + 1, w * acc[mi][ni][half * 2 + 1]);
            }
        }
    }
}

// ---------------------------------------------------------------------------
extern "C" void kernel_launch(void* const* d_in, const int* in_sizes, int n_in,
                              void* d_out, int out_size) {
    const float* x  = (const float*)d_in[0];
    const float* Wr = (const float*)d_in[1];
    const float* Wg = (const float*)d_in[2];
    const float* Wu = (const float*)d_in[3];
    const float* Wd = (const float*)d_in[4];
    float* out = (float*)d_out;

    cudaFuncSetAttribute(gateup_tc, cudaFuncAttributeMaxDynamicSharedMemorySize, GU_SMEM);
    cudaFuncSetAttribute(down_tc,   cudaFuncAttributeMaxDynamicSharedMemorySize, DN_SMEM);

    prep_kernel<<<2048, 256>>>(x, out);                               // 0
    router_kernel<<<NT, 256>>>(x, Wr);                                // 1 (router+compact)
    wpack_kernel<<<3 * NE * 16384, dim3(32, 8)>>>(Wg, Wu, Wd);        // 2
    gateup_tc<<<dim3(NT/128, NF/128, NE), 256, GU_SMEM>>>();          // 3 (profiled slot)
    down_tc  <<<dim3(NT/128, ND/128, NE), 256, DN_SMEM>>>(out);       // 4
}